// round 15
// baseline (speedup 1.0000x reference)
#include <cuda_runtime.h>
#include <cuda_bf16.h>
#include <cstdint>

// HyperedgeMeanAggregator: out[h,:] = mean_{e: seg_ids[e]==h} embed_table[node_idx[e],:]
// seg_ids SORTED, indices int32 (JAX x64 off).
//
// SINGLE kernel. Block owns 32 consecutive hyperedges (8 warps x SEGW=4).
// Prologue: threads 0..32 run the 33 boundary lower_bounds in PARALLEL into
// shared memory (~21 L2-hot steps each, overlapped chip-wide) -> no seg_start
// kernel, no extra launch, no offsets round-trip. Main loop: per-segment
// known-count unroll-8 gather (best measured), one STG.128 flush of acc/cnt.
// No atomics, no memset, no divide pass. Output stores use .cs and index loads
// .cs to keep the 100MB table resident in L2.

#define FEAT   128
#define FEAT4  (FEAT / 4)     // 32 float4 per row = one warp
#define SEGW   4              // segments per warp
#define BLOCK  256            // 8 warps per block
#define WARPS  (BLOCK / 32)
#define SEGB   (WARPS * SEGW) // 32 segments per block

__device__ __forceinline__ int ldcs_i(const int* p) {
    int v;
    asm volatile("ld.global.cs.b32 %0, [%1];" : "=r"(v) : "l"(p));
    return v;
}
__device__ __forceinline__ void stcs_f4(float4* p, float4 v) {
    asm volatile("st.global.cs.v4.f32 [%0], {%1, %2, %3, %4};"
                 :: "l"(p), "f"(v.x), "f"(v.y), "f"(v.z), "f"(v.w));
}

__global__ __launch_bounds__(BLOCK)
void agg_kernel(const float* __restrict__ table,
                const int* __restrict__ node_idx,
                const int* __restrict__ seg_ids,
                float* __restrict__ out,
                int E, int H) {
    __shared__ int bs[SEGB + 1];

    int tid  = threadIdx.x;
    int wid  = tid >> 5;
    int lane = tid & 31;

    int block_h0 = blockIdx.x * SEGB;
    if (block_h0 >= H) return;

    // Parallel boundary searches: thread t finds lower_bound(seg_ids, block_h0+t).
    if (tid <= SEGB) {
        int key = block_h0 + tid;
        if (key >= H) {
            bs[tid] = E;
        } else {
            int lo = 0, hi = E;
            while (lo < hi) {
                int mid = (lo + hi) >> 1;
                if (__ldg(&seg_ids[mid]) < key) lo = mid + 1; else hi = mid;
            }
            bs[tid] = lo;
        }
    }
    __syncthreads();

    const float4* t4 = reinterpret_cast<const float4*>(table);
    float4* o4 = reinterpret_cast<float4*>(out);

    int h_lo = block_h0 + wid * SEGW;
    if (h_lo >= H) return;
    int h_hi = h_lo + SEGW; if (h_hi > H) h_hi = H;

    int eb = bs[wid * SEGW];

    for (int h = h_lo; h < h_hi; ++h) {
        int ee = bs[h - block_h0 + 1];
        int cnt = ee - eb;

        float4 acc = make_float4(0.f, 0.f, 0.f, 0.f);

        int e = eb;
        for (; e + 8 <= ee; e += 8) {
            unsigned n0 = (unsigned)ldcs_i(&node_idx[e + 0]) * FEAT4 + lane;
            unsigned n1 = (unsigned)ldcs_i(&node_idx[e + 1]) * FEAT4 + lane;
            unsigned n2 = (unsigned)ldcs_i(&node_idx[e + 2]) * FEAT4 + lane;
            unsigned n3 = (unsigned)ldcs_i(&node_idx[e + 3]) * FEAT4 + lane;
            unsigned n4 = (unsigned)ldcs_i(&node_idx[e + 4]) * FEAT4 + lane;
            unsigned n5 = (unsigned)ldcs_i(&node_idx[e + 5]) * FEAT4 + lane;
            unsigned n6 = (unsigned)ldcs_i(&node_idx[e + 6]) * FEAT4 + lane;
            unsigned n7 = (unsigned)ldcs_i(&node_idx[e + 7]) * FEAT4 + lane;
            // All 8 row gathers issued before any consumption -> MLP=8.
            float4 v0 = __ldg(&t4[n0]);
            float4 v1 = __ldg(&t4[n1]);
            float4 v2 = __ldg(&t4[n2]);
            float4 v3 = __ldg(&t4[n3]);
            float4 v4 = __ldg(&t4[n4]);
            float4 v5 = __ldg(&t4[n5]);
            float4 v6 = __ldg(&t4[n6]);
            float4 v7 = __ldg(&t4[n7]);
            acc.x += v0.x; acc.y += v0.y; acc.z += v0.z; acc.w += v0.w;
            acc.x += v1.x; acc.y += v1.y; acc.z += v1.z; acc.w += v1.w;
            acc.x += v2.x; acc.y += v2.y; acc.z += v2.z; acc.w += v2.w;
            acc.x += v3.x; acc.y += v3.y; acc.z += v3.z; acc.w += v3.w;
            acc.x += v4.x; acc.y += v4.y; acc.z += v4.z; acc.w += v4.w;
            acc.x += v5.x; acc.y += v5.y; acc.z += v5.z; acc.w += v5.w;
            acc.x += v6.x; acc.y += v6.y; acc.z += v6.z; acc.w += v6.w;
            acc.x += v7.x; acc.y += v7.y; acc.z += v7.z; acc.w += v7.w;
        }
        if (e + 4 <= ee) {
            unsigned n0 = (unsigned)ldcs_i(&node_idx[e + 0]) * FEAT4 + lane;
            unsigned n1 = (unsigned)ldcs_i(&node_idx[e + 1]) * FEAT4 + lane;
            unsigned n2 = (unsigned)ldcs_i(&node_idx[e + 2]) * FEAT4 + lane;
            unsigned n3 = (unsigned)ldcs_i(&node_idx[e + 3]) * FEAT4 + lane;
            float4 v0 = __ldg(&t4[n0]);
            float4 v1 = __ldg(&t4[n1]);
            float4 v2 = __ldg(&t4[n2]);
            float4 v3 = __ldg(&t4[n3]);
            acc.x += v0.x; acc.y += v0.y; acc.z += v0.z; acc.w += v0.w;
            acc.x += v1.x; acc.y += v1.y; acc.z += v1.z; acc.w += v1.w;
            acc.x += v2.x; acc.y += v2.y; acc.z += v2.z; acc.w += v2.w;
            acc.x += v3.x; acc.y += v3.y; acc.z += v3.z; acc.w += v3.w;
            e += 4;
        }
        for (; e < ee; ++e) {
            unsigned n = (unsigned)ldcs_i(&node_idx[e]) * FEAT4 + lane;
            float4 v = __ldg(&t4[n]);
            acc.x += v.x; acc.y += v.y; acc.z += v.z; acc.w += v.w;
        }

        float inv = 1.0f / (float)max(cnt, 1);     // empty segment -> zeros
        stcs_f4(&o4[(unsigned)h * FEAT4 + lane],
                make_float4(acc.x * inv, acc.y * inv, acc.z * inv, acc.w * inv));

        eb = ee;
    }
}

extern "C" void kernel_launch(void* const* d_in, const int* in_sizes, int n_in,
                              void* d_out, int out_size) {
    const float* table    = (const float*)d_in[0];
    const int*   node_idx = (const int*)d_in[1];
    const int*   seg_ids  = (const int*)d_in[2];
    float*       out      = (float*)d_out;

    int E = in_sizes[1];
    int H = out_size / FEAT;

    int blocks = (H + SEGB - 1) / SEGB;
    agg_kernel<<<blocks, BLOCK>>>(table, node_idx, seg_ids, out, E, H);
}

// round 16
// speedup vs baseline: 1.1409x; 1.1409x over previous
#include <cuda_runtime.h>
#include <cuda_bf16.h>
#include <cstdint>

// HyperedgeMeanAggregator: out[h,:] = mean_{e: seg_ids[e]==h} embed_table[node_idx[e],:]
// seg_ids SORTED, indices int32 (JAX x64 off).
//
// Two kernels:
//  1) boundary diff-scan: seg_start[h] for all h from one coalesced pass over
//     seg_ids (no binary searches).
//  2) ownership agg (R14 measured-best): warp owns 4 segments, per-segment
//     known-count unroll-8 gather (MLP=8), one .cs STG.128 flush of acc/cnt.
//     No atomics, no memset, no divide pass.

#define FEAT   128
#define FEAT4  (FEAT / 4)     // 32 float4 per row = one warp
#define SEGW   4              // segments per warp
#define BLOCK  256            // 8 warps per block
#define WARPS  (BLOCK / 32)
#define MAX_H  65536

__device__ int g_seg_start[MAX_H + 1];

// seg_start[h] = first entry index with seg_ids[e] >= h.
// Thread e fills seg_start[h] = e for h in (seg_ids[e-1], seg_ids[e]].
__global__ __launch_bounds__(256)
void boundary_kernel(const int* __restrict__ seg_ids, int E, int H) {
    int e = blockIdx.x * blockDim.x + threadIdx.x;
    if (e >= E) return;
    int cur  = __ldg(&seg_ids[e]);
    int prev = (e == 0) ? -1 : __ldg(&seg_ids[e - 1]);
    for (int h = prev + 1; h <= cur; ++h)
        g_seg_start[h] = e;
    if (e == E - 1) {
        for (int h = cur + 1; h <= H; ++h)
            g_seg_start[h] = E;
    }
}

__device__ __forceinline__ void stcs_f4(float4* p, float4 v) {
    asm volatile("st.global.cs.v4.f32 [%0], {%1, %2, %3, %4};"
                 :: "l"(p), "f"(v.x), "f"(v.y), "f"(v.z), "f"(v.w));
}

__global__ __launch_bounds__(BLOCK)
void agg_kernel(const float* __restrict__ table,
                const int* __restrict__ node_idx,
                float* __restrict__ out,
                int H) {
    int gwarp = (blockIdx.x * blockDim.x + threadIdx.x) >> 5;
    int lane  = threadIdx.x & 31;

    int h_lo = gwarp * SEGW;
    if (h_lo >= H) return;
    int h_hi = h_lo + SEGW; if (h_hi > H) h_hi = H;

    const float4* t4 = reinterpret_cast<const float4*>(table);
    float4* o4 = reinterpret_cast<float4*>(out);

    int eb = __ldg(&g_seg_start[h_lo]);

    for (int h = h_lo; h < h_hi; ++h) {
        int ee = __ldg(&g_seg_start[h + 1]);
        int cnt = ee - eb;

        float4 acc = make_float4(0.f, 0.f, 0.f, 0.f);

        int e = eb;
        for (; e + 8 <= ee; e += 8) {
            unsigned n0 = (unsigned)__ldg(&node_idx[e + 0]) * FEAT4 + lane;
            unsigned n1 = (unsigned)__ldg(&node_idx[e + 1]) * FEAT4 + lane;
            unsigned n2 = (unsigned)__ldg(&node_idx[e + 2]) * FEAT4 + lane;
            unsigned n3 = (unsigned)__ldg(&node_idx[e + 3]) * FEAT4 + lane;
            unsigned n4 = (unsigned)__ldg(&node_idx[e + 4]) * FEAT4 + lane;
            unsigned n5 = (unsigned)__ldg(&node_idx[e + 5]) * FEAT4 + lane;
            unsigned n6 = (unsigned)__ldg(&node_idx[e + 6]) * FEAT4 + lane;
            unsigned n7 = (unsigned)__ldg(&node_idx[e + 7]) * FEAT4 + lane;
            // All 8 row gathers issued before any consumption -> MLP=8.
            float4 v0 = __ldg(&t4[n0]);
            float4 v1 = __ldg(&t4[n1]);
            float4 v2 = __ldg(&t4[n2]);
            float4 v3 = __ldg(&t4[n3]);
            float4 v4 = __ldg(&t4[n4]);
            float4 v5 = __ldg(&t4[n5]);
            float4 v6 = __ldg(&t4[n6]);
            float4 v7 = __ldg(&t4[n7]);
            acc.x += v0.x; acc.y += v0.y; acc.z += v0.z; acc.w += v0.w;
            acc.x += v1.x; acc.y += v1.y; acc.z += v1.z; acc.w += v1.w;
            acc.x += v2.x; acc.y += v2.y; acc.z += v2.z; acc.w += v2.w;
            acc.x += v3.x; acc.y += v3.y; acc.z += v3.z; acc.w += v3.w;
            acc.x += v4.x; acc.y += v4.y; acc.z += v4.z; acc.w += v4.w;
            acc.x += v5.x; acc.y += v5.y; acc.z += v5.z; acc.w += v5.w;
            acc.x += v6.x; acc.y += v6.y; acc.z += v6.z; acc.w += v6.w;
            acc.x += v7.x; acc.y += v7.y; acc.z += v7.z; acc.w += v7.w;
        }
        if (e + 4 <= ee) {
            unsigned n0 = (unsigned)__ldg(&node_idx[e + 0]) * FEAT4 + lane;
            unsigned n1 = (unsigned)__ldg(&node_idx[e + 1]) * FEAT4 + lane;
            unsigned n2 = (unsigned)__ldg(&node_idx[e + 2]) * FEAT4 + lane;
            unsigned n3 = (unsigned)__ldg(&node_idx[e + 3]) * FEAT4 + lane;
            float4 v0 = __ldg(&t4[n0]);
            float4 v1 = __ldg(&t4[n1]);
            float4 v2 = __ldg(&t4[n2]);
            float4 v3 = __ldg(&t4[n3]);
            acc.x += v0.x; acc.y += v0.y; acc.z += v0.z; acc.w += v0.w;
            acc.x += v1.x; acc.y += v1.y; acc.z += v1.z; acc.w += v1.w;
            acc.x += v2.x; acc.y += v2.y; acc.z += v2.z; acc.w += v2.w;
            acc.x += v3.x; acc.y += v3.y; acc.z += v3.z; acc.w += v3.w;
            e += 4;
        }
        for (; e < ee; ++e) {
            unsigned n = (unsigned)__ldg(&node_idx[e]) * FEAT4 + lane;
            float4 v = __ldg(&t4[n]);
            acc.x += v.x; acc.y += v.y; acc.z += v.z; acc.w += v.w;
        }

        float inv = 1.0f / (float)max(cnt, 1);     // empty segment -> zeros
        stcs_f4(&o4[(unsigned)h * FEAT4 + lane],
                make_float4(acc.x * inv, acc.y * inv, acc.z * inv, acc.w * inv));

        eb = ee;
    }
}

extern "C" void kernel_launch(void* const* d_in, const int* in_sizes, int n_in,
                              void* d_out, int out_size) {
    const float* table    = (const float*)d_in[0];
    const int*   node_idx = (const int*)d_in[1];
    const int*   seg_ids  = (const int*)d_in[2];
    float*       out      = (float*)d_out;

    int E = in_sizes[1];
    int H = out_size / FEAT;

    // 1) per-segment start offsets via coalesced diff-scan
    boundary_kernel<<<(E + 255) / 256, 256>>>(seg_ids, E, H);

    // 2) gather + per-segment mean, direct writes
    {
        int warps  = (H + SEGW - 1) / SEGW;
        int blocks = (warps + WARPS - 1) / WARPS;
        agg_kernel<<<blocks, BLOCK>>>(table, node_idx, out, H);
    }
}

// round 17
// speedup vs baseline: 1.1943x; 1.0468x over previous
#include <cuda_runtime.h>
#include <cuda_bf16.h>
#include <cstdint>

// HyperedgeMeanAggregator: out[h,:] = mean_{e: seg_ids[e]==h} embed_table[node_idx[e],:]
// seg_ids SORTED, indices int32 (JAX x64 off).
//
// Two kernels:
//  1) boundary diff-scan: seg_start[h] from one coalesced pass (no searches).
//  2) ownership agg: warp owns 4 segments. Per segment: unroll-8 gather with
//     TRUE MLP=8 (reg budget 64 via launch_bounds(256,4)) and software-
//     pipelined index loads (next block's indices fetched under current
//     block's gathers). One .cs STG.128 flush of acc/cnt. No atomics, no
//     memset, no divide pass.

#define FEAT   128
#define FEAT4  (FEAT / 4)     // 32 float4 per row = one warp
#define SEGW   4              // segments per warp
#define BLOCK  256            // 8 warps per block
#define WARPS  (BLOCK / 32)
#define MAX_H  65536

__device__ int g_seg_start[MAX_H + 1];

// seg_start[h] = first entry index with seg_ids[e] >= h.
__global__ __launch_bounds__(256)
void boundary_kernel(const int* __restrict__ seg_ids, int E, int H) {
    int e = blockIdx.x * blockDim.x + threadIdx.x;
    if (e >= E) return;
    int cur  = __ldg(&seg_ids[e]);
    int prev = (e == 0) ? -1 : __ldg(&seg_ids[e - 1]);
    for (int h = prev + 1; h <= cur; ++h)
        g_seg_start[h] = e;
    if (e == E - 1) {
        for (int h = cur + 1; h <= H; ++h)
            g_seg_start[h] = E;
    }
}

__device__ __forceinline__ void stcs_f4(float4* p, float4 v) {
    asm volatile("st.global.cs.v4.f32 [%0], {%1, %2, %3, %4};"
                 :: "l"(p), "f"(v.x), "f"(v.y), "f"(v.z), "f"(v.w));
}

__global__ __launch_bounds__(BLOCK, 4)   // reg budget 64: keep 8 float4 loads live
void agg_kernel(const float* __restrict__ table,
                const int* __restrict__ node_idx,
                float* __restrict__ out,
                int H) {
    int gwarp = (blockIdx.x * blockDim.x + threadIdx.x) >> 5;
    int lane  = threadIdx.x & 31;

    int h_lo = gwarp * SEGW;
    if (h_lo >= H) return;
    int h_hi = h_lo + SEGW; if (h_hi > H) h_hi = H;

    const float4* t4 = reinterpret_cast<const float4*>(table);
    float4* o4 = reinterpret_cast<float4*>(out);

    int eb = __ldg(&g_seg_start[h_lo]);

    for (int h = h_lo; h < h_hi; ++h) {
        int ee = __ldg(&g_seg_start[h + 1]);
        int cnt = ee - eb;

        float4 acc = make_float4(0.f, 0.f, 0.f, 0.f);

        int e = eb;
        int nfull = (ee - eb) >> 3;          // number of full 8-blocks

        if (nfull > 0) {
            // Preload indices for block 0.
            unsigned i0 = (unsigned)__ldg(&node_idx[e + 0]) * FEAT4 + lane;
            unsigned i1 = (unsigned)__ldg(&node_idx[e + 1]) * FEAT4 + lane;
            unsigned i2 = (unsigned)__ldg(&node_idx[e + 2]) * FEAT4 + lane;
            unsigned i3 = (unsigned)__ldg(&node_idx[e + 3]) * FEAT4 + lane;
            unsigned i4 = (unsigned)__ldg(&node_idx[e + 4]) * FEAT4 + lane;
            unsigned i5 = (unsigned)__ldg(&node_idx[e + 5]) * FEAT4 + lane;
            unsigned i6 = (unsigned)__ldg(&node_idx[e + 6]) * FEAT4 + lane;
            unsigned i7 = (unsigned)__ldg(&node_idx[e + 7]) * FEAT4 + lane;

            for (int b = 0; b < nfull; ++b) {
                // Issue all 8 row gathers (MLP=8).
                float4 v0 = __ldg(&t4[i0]);
                float4 v1 = __ldg(&t4[i1]);
                float4 v2 = __ldg(&t4[i2]);
                float4 v3 = __ldg(&t4[i3]);
                float4 v4 = __ldg(&t4[i4]);
                float4 v5 = __ldg(&t4[i5]);
                float4 v6 = __ldg(&t4[i6]);
                float4 v7 = __ldg(&t4[i7]);

                // Prefetch next block's indices UNDER the gathers' latency.
                int ep = e + 8;
                if (b + 1 < nfull) {
                    i0 = (unsigned)__ldg(&node_idx[ep + 0]) * FEAT4 + lane;
                    i1 = (unsigned)__ldg(&node_idx[ep + 1]) * FEAT4 + lane;
                    i2 = (unsigned)__ldg(&node_idx[ep + 2]) * FEAT4 + lane;
                    i3 = (unsigned)__ldg(&node_idx[ep + 3]) * FEAT4 + lane;
                    i4 = (unsigned)__ldg(&node_idx[ep + 4]) * FEAT4 + lane;
                    i5 = (unsigned)__ldg(&node_idx[ep + 5]) * FEAT4 + lane;
                    i6 = (unsigned)__ldg(&node_idx[ep + 6]) * FEAT4 + lane;
                    i7 = (unsigned)__ldg(&node_idx[ep + 7]) * FEAT4 + lane;
                }

                acc.x += v0.x; acc.y += v0.y; acc.z += v0.z; acc.w += v0.w;
                acc.x += v1.x; acc.y += v1.y; acc.z += v1.z; acc.w += v1.w;
                acc.x += v2.x; acc.y += v2.y; acc.z += v2.z; acc.w += v2.w;
                acc.x += v3.x; acc.y += v3.y; acc.z += v3.z; acc.w += v3.w;
                acc.x += v4.x; acc.y += v4.y; acc.z += v4.z; acc.w += v4.w;
                acc.x += v5.x; acc.y += v5.y; acc.z += v5.z; acc.w += v5.w;
                acc.x += v6.x; acc.y += v6.y; acc.z += v6.z; acc.w += v6.w;
                acc.x += v7.x; acc.y += v7.y; acc.z += v7.z; acc.w += v7.w;
                e = ep;
            }
        }
        if (e + 4 <= ee) {
            unsigned n0 = (unsigned)__ldg(&node_idx[e + 0]) * FEAT4 + lane;
            unsigned n1 = (unsigned)__ldg(&node_idx[e + 1]) * FEAT4 + lane;
            unsigned n2 = (unsigned)__ldg(&node_idx[e + 2]) * FEAT4 + lane;
            unsigned n3 = (unsigned)__ldg(&node_idx[e + 3]) * FEAT4 + lane;
            float4 v0 = __ldg(&t4[n0]);
            float4 v1 = __ldg(&t4[n1]);
            float4 v2 = __ldg(&t4[n2]);
            float4 v3 = __ldg(&t4[n3]);
            acc.x += v0.x; acc.y += v0.y; acc.z += v0.z; acc.w += v0.w;
            acc.x += v1.x; acc.y += v1.y; acc.z += v1.z; acc.w += v1.w;
            acc.x += v2.x; acc.y += v2.y; acc.z += v2.z; acc.w += v2.w;
            acc.x += v3.x; acc.y += v3.y; acc.z += v3.z; acc.w += v3.w;
            e += 4;
        }
        for (; e < ee; ++e) {
            unsigned n = (unsigned)__ldg(&node_idx[e]) * FEAT4 + lane;
            float4 v = __ldg(&t4[n]);
            acc.x += v.x; acc.y += v.y; acc.z += v.z; acc.w += v.w;
        }

        float inv = 1.0f / (float)max(cnt, 1);     // empty segment -> zeros
        stcs_f4(&o4[(unsigned)h * FEAT4 + lane],
                make_float4(acc.x * inv, acc.y * inv, acc.z * inv, acc.w * inv));

        eb = ee;
    }
}

extern "C" void kernel_launch(void* const* d_in, const int* in_sizes, int n_in,
                              void* d_out, int out_size) {
    const float* table    = (const float*)d_in[0];
    const int*   node_idx = (const int*)d_in[1];
    const int*   seg_ids  = (const int*)d_in[2];
    float*       out      = (float*)d_out;

    int E = in_sizes[1];
    int H = out_size / FEAT;

    // 1) per-segment start offsets via coalesced diff-scan
    boundary_kernel<<<(E + 255) / 256, 256>>>(seg_ids, E, H);

    // 2) gather + per-segment mean, direct writes
    {
        int warps  = (H + SEGW - 1) / SEGW;
        int blocks = (warps + WARPS - 1) / WARPS;
        agg_kernel<<<blocks, BLOCK>>>(table, node_idx, out, H);
    }
}